// round 1
// baseline (speedup 1.0000x reference)
#include <cuda_runtime.h>

typedef unsigned long long ull;

#define NTHR   256
#define TLEN   168
#define SEQ    169
#define NH     64
#define NG     256
#define NSTEPS 24
#define NBMAX  32
#define WINBUF 192   // 168 window + 24 appended outputs
#define NUNIT  8     // ceil(NBMAX*64 / 256)

// relu(h1) staging buffer: [4096][168][64] fp32 = 176 MB
__device__ float g_r1[(size_t)4096 * TLEN * NH];

static __device__ __forceinline__ void ffma2(ull& d, ull a, ull b) {
    asm("fma.rn.f32x2 %0, %1, %2, %0;" : "+l"(d) : "l"(a), "l"(b));
}
static __device__ __forceinline__ ull fadd2(ull a, ull b) {
    ull r; asm("add.rn.f32x2 %0, %1, %2;" : "=l"(r) : "l"(a), "l"(b)); return r;
}
static __device__ __forceinline__ float2 unpack2(ull v) {
    float2 r; asm("mov.b64 {%0, %1}, %2;" : "=f"(r.x), "=f"(r.y) : "l"(v)); return r;
}
static __device__ __forceinline__ float rcp_fast(float x) {
    float r; asm("rcp.approx.f32 %0, %1;" : "=f"(r) : "f"(x)); return r;
}
static __device__ __forceinline__ float sig_fast(float x) {
    return rcp_fast(1.0f + __expf(-x));
}
static __device__ __forceinline__ float tanh_fast(float x) {
    // tanh(x) = 2*sigmoid(2x) - 1  (inf-safe at both ends)
    return fmaf(2.0f, sig_fast(2.0f * x), -1.0f);
}

__global__ void __launch_bounds__(NTHR, 1)
lstm_rec_kernel(const float* __restrict__ x,
                const float* __restrict__ Wih1, const float* __restrict__ Whh1,
                const float* __restrict__ bih1, const float* __restrict__ bhh1,
                const float* __restrict__ Wih2, const float* __restrict__ Whh2,
                const float* __restrict__ bih2, const float* __restrict__ bhh2,
                const float* __restrict__ fc1w, const float* __restrict__ fc1b,
                const float* __restrict__ fc2w, const float* __restrict__ fc2b,
                float* __restrict__ out,
                int nb_base, int rem)
{
    const int tid = threadIdx.x;
    const int bid = blockIdx.x;
    const int nb  = nb_base + (bid < rem ? 1 : 0);
    const int b0  = bid * nb_base + (bid < rem ? bid : rem);
    const int nbu = nb * NH;

    extern __shared__ float sm[];
    float* win_sh = sm;                       // [NBMAX][WINBUF]
    float* hh     = win_sh + NBMAX * WINBUF;  // [NBMAX][128]: [0..63]=r1_t, [64..127]=h
    float* g_sh   = hh + NBMAX * 128;         // [NBMAX][NG]
    float* wcomb  = g_sh + NBMAX * NG;        // [65]
    float* bcomb  = wcomb + 65;               // [1]
    float* d_sh   = bcomb + 1;                // [NBMAX]

    // ---------------- one-time init ----------------
    for (int i = tid; i < nb * TLEN; i += NTHR) {
        int b = i / TLEN, t = i - b * TLEN;
        win_sh[b * WINBUF + t] = x[(size_t)(b0 + b) * SEQ + t];
    }
    for (int i = tid; i < nb; i += NTHR)
        d_sh[i] = x[(size_t)(b0 + i) * SEQ + TLEN];
    for (int i = tid; i < nb * 128; i += NTHR) hh[i] = 0.0f;
    if (tid < 65) {
        // fc collapse: out = wcomb . [relu(h2_T), d] + bcomb
        float s = 0.0f;
        for (int jj = 0; jj < 64; jj++) s = fmaf(fc2w[jj], fc1w[jj * 65 + tid], s);
        wcomb[tid] = s;
    }
    if (tid == 65) {
        float s = fc2b[0];
        for (int jj = 0; jj < 64; jj++) s = fmaf(fc2w[jj], fc1b[jj], s);
        *bcomb = s;
    }

    const int   j   = tid;                   // gate row owned by this thread
    const float b1  = bih1[j] + bhh1[j];
    const float b2  = bih2[j] + bhh2[j];
    const float wi1 = Wih1[j];

    float c[NUNIT];                          // cell state, carried layer1 -> layer2
    __syncthreads();

    for (int step = 0; step < NSTEPS; step++) {
        // ============ layer 1: 168-step recurrence ============
        {
            const float* wq = Whh1; asm("" : "+l"(wq));  // prevent hoist across phases
            ull w1[32];
            {
                const ulonglong2* wp = (const ulonglong2*)(wq + j * NH);
                #pragma unroll
                for (int q = 0; q < 16; q++) { ulonglong2 v = wp[q]; w1[2*q] = v.x; w1[2*q+1] = v.y; }
            }
            // h1_0 = 0, c1_0 = 0
            for (int i = tid; i < nbu; i += NTHR) { int b = i >> 6, u = i & 63; hh[b*128 + 64 + u] = 0.0f; }
            #pragma unroll
            for (int r = 0; r < NUNIT; r++) c[r] = 0.0f;
            __syncthreads();

            for (int t = 0; t < TLEN; t++) {
                // g_j[b] = Whh1[j,:] . h1[b] + x_t[b]*Wih1[j] + b1
                for (int b = 0; b < nb; b++) {
                    const ulonglong2* hp = (const ulonglong2*)(hh + b * 128 + 64);
                    ull a0 = 0, a1 = 0, a2 = 0, a3 = 0;
                    #pragma unroll
                    for (int kk = 0; kk < 16; kk++) {
                        ulonglong2 v = hp[kk];
                        if (kk & 1) { ffma2(a2, w1[2*kk], v.x); ffma2(a3, w1[2*kk+1], v.y); }
                        else        { ffma2(a0, w1[2*kk], v.x); ffma2(a1, w1[2*kk+1], v.y); }
                    }
                    float2 f = unpack2(fadd2(fadd2(a0, a1), fadd2(a2, a3)));
                    float xt = win_sh[b * WINBUF + step + t];
                    g_sh[b * NG + j] = (f.x + f.y) + fmaf(xt, wi1, b1);
                }
                __syncthreads();
                // activations: unit (b,u) -> thread tid = (b*64+u) % 256
                #pragma unroll
                for (int r = 0; r < NUNIT; r++) {
                    int i_lin = tid + NTHR * r;
                    if (i_lin < nbu) {
                        int b = i_lin >> 6, u = i_lin & 63;
                        const float* gb = g_sh + b * NG + u;
                        float si = sig_fast(gb[0]);
                        float sf = sig_fast(gb[64]);
                        float tg = tanh_fast(gb[128]);
                        float so = sig_fast(gb[192]);
                        float cn = fmaf(sf, c[r], si * tg);
                        c[r] = cn;
                        float h = so * tanh_fast(cn);
                        hh[b * 128 + 64 + u] = h;
                        g_r1[((size_t)(b0 + b) * TLEN + t) * NH + u] = fmaxf(h, 0.0f);
                    }
                }
                __syncthreads();
            }
        }
        // ============ layer 2: 168-step recurrence (h2_0 = h1_T, c2_0 = c1_T) ============
        {
            const float* p1 = Wih2; asm("" : "+l"(p1));
            const float* p2 = Whh2; asm("" : "+l"(p2));
            ull w2[64];  // [Wih2_row | Whh2_row] -> single 128-wide dot vs [r1_t | h2]
            {
                const ulonglong2* a  = (const ulonglong2*)(p1 + j * NH);
                const ulonglong2* bq = (const ulonglong2*)(p2 + j * NH);
                #pragma unroll
                for (int q = 0; q < 16; q++) { ulonglong2 v = a[q];  w2[2*q]      = v.x; w2[2*q+1]      = v.y; }
                #pragma unroll
                for (int q = 0; q < 16; q++) { ulonglong2 v = bq[q]; w2[32 + 2*q] = v.x; w2[32 + 2*q+1] = v.y; }
            }
            // prefetch r1 for t=0 (same thread wrote it -> no fence needed)
            float r1v[NUNIT];
            #pragma unroll
            for (int r = 0; r < NUNIT; r++) {
                int i_lin = tid + NTHR * r;
                if (i_lin < nbu) {
                    int b = i_lin >> 6, u = i_lin & 63;
                    r1v[r] = g_r1[((size_t)(b0 + b) * TLEN) * NH + u];
                }
            }
            for (int t = 0; t < TLEN; t++) {
                #pragma unroll
                for (int r = 0; r < NUNIT; r++) {
                    int i_lin = tid + NTHR * r;
                    if (i_lin < nbu) { int b = i_lin >> 6, u = i_lin & 63; hh[b * 128 + u] = r1v[r]; }
                }
                __syncthreads();
                if (t + 1 < TLEN) {  // prefetch next r1 under the matvec
                    #pragma unroll
                    for (int r = 0; r < NUNIT; r++) {
                        int i_lin = tid + NTHR * r;
                        if (i_lin < nbu) {
                            int b = i_lin >> 6, u = i_lin & 63;
                            r1v[r] = g_r1[((size_t)(b0 + b) * TLEN + (t + 1)) * NH + u];
                        }
                    }
                }
                for (int b = 0; b < nb; b++) {
                    const ulonglong2* hp = (const ulonglong2*)(hh + b * 128);
                    ull a0 = 0, a1 = 0, a2 = 0, a3 = 0;
                    #pragma unroll
                    for (int kk = 0; kk < 32; kk++) {
                        ulonglong2 v = hp[kk];
                        if (kk & 1) { ffma2(a2, w2[2*kk], v.x); ffma2(a3, w2[2*kk+1], v.y); }
                        else        { ffma2(a0, w2[2*kk], v.x); ffma2(a1, w2[2*kk+1], v.y); }
                    }
                    float2 f = unpack2(fadd2(fadd2(a0, a1), fadd2(a2, a3)));
                    g_sh[b * NG + j] = (f.x + f.y) + b2;
                }
                __syncthreads();
                #pragma unroll
                for (int r = 0; r < NUNIT; r++) {
                    int i_lin = tid + NTHR * r;
                    if (i_lin < nbu) {
                        int b = i_lin >> 6, u = i_lin & 63;
                        const float* gb = g_sh + b * NG + u;
                        float si = sig_fast(gb[0]);
                        float sf = sig_fast(gb[64]);
                        float tg = tanh_fast(gb[128]);
                        float so = sig_fast(gb[192]);
                        float cn = fmaf(sf, c[r], si * tg);
                        c[r] = cn;
                        hh[b * 128 + 64 + u] = so * tanh_fast(cn);
                    }
                }
                // no sync here: next-iter top sync orders hh-upper writes before matvec
            }
            __syncthreads();
        }
        // ============ FC (collapsed) + window append ============
        if (tid < nb) {
            int b = tid;
            float s = *bcomb + wcomb[64] * d_sh[b];
            #pragma unroll
            for (int u = 0; u < 64; u++)
                s = fmaf(wcomb[u], fmaxf(hh[b * 128 + 64 + u], 0.0f), s);
            out[(size_t)(b0 + b) * NSTEPS + step] = s;
            win_sh[b * WINBUF + TLEN + step] = s;
        }
        __syncthreads();
    }
}

extern "C" void kernel_launch(void* const* d_in, const int* in_sizes, int n_in,
                              void* d_out, int out_size) {
    (void)in_sizes; (void)n_in; (void)out_size;
    const float* x    = (const float*)d_in[0];
    const float* Wih1 = (const float*)d_in[1];
    const float* Whh1 = (const float*)d_in[2];
    const float* bih1 = (const float*)d_in[3];
    const float* bhh1 = (const float*)d_in[4];
    const float* Wih2 = (const float*)d_in[5];
    const float* Whh2 = (const float*)d_in[6];
    const float* bih2 = (const float*)d_in[7];
    const float* bhh2 = (const float*)d_in[8];
    const float* fc1w = (const float*)d_in[9];
    const float* fc1b = (const float*)d_in[10];
    const float* fc2w = (const float*)d_in[11];
    const float* fc2b = (const float*)d_in[12];
    float* out = (float*)d_out;

    int dev = 0, sms = 148;
    cudaGetDevice(&dev);
    cudaDeviceGetAttribute(&sms, cudaDevAttrMultiProcessorCount, dev);
    int grid = sms < 128 ? 128 : (sms > 160 ? 160 : sms);  // one CTA per SM, one wave
    int nb_base = 4096 / grid;
    int rem     = 4096 - grid * nb_base;

    size_t smem = (size_t)(NBMAX * WINBUF + NBMAX * 128 + NBMAX * NG + 65 + 1 + NBMAX) * sizeof(float);
    cudaFuncSetAttribute(lstm_rec_kernel, cudaFuncAttributeMaxDynamicSharedMemorySize, (int)smem);
    lstm_rec_kernel<<<grid, NTHR, smem>>>(x, Wih1, Whh1, bih1, bhh1,
                                          Wih2, Whh2, bih2, bhh2,
                                          fc1w, fc1b, fc2w, fc2b,
                                          out, nb_base, rem);
}

// round 2
// speedup vs baseline: 1.3591x; 1.3591x over previous
#include <cuda_runtime.h>

typedef unsigned long long ull;

#define NTHR   256
#define TLEN   168
#define SEQ    169
#define NB     32      // batches per CTA
#define GRID   128     // 128 * 32 = 4096
#define NSTEPS 24
#define WSTR   193     // window row stride (pad for conflict-free)
#define GSTR   36      // g_sh row stride (pad)

// relu(h1) staging: [GRID][TLEN][64][NB] fp32 = 176 MB
__device__ float g_r1[(size_t)GRID * TLEN * 64 * NB];

static __device__ __forceinline__ void ffma2(ull& d, ull a, ull b) {
    asm("fma.rn.f32x2 %0, %1, %2, %0;" : "+l"(d) : "l"(a), "l"(b));
}
static __device__ __forceinline__ ull splat(float w) {
    ull r; asm("mov.b64 %0, {%1, %1};" : "=l"(r) : "f"(w)); return r;
}
static __device__ __forceinline__ float rcp_fast(float x) {
    float r; asm("rcp.approx.f32 %0, %1;" : "=f"(r) : "f"(x)); return r;
}
static __device__ __forceinline__ float sig_fast(float x) {
    return rcp_fast(1.0f + __expf(-x));
}
static __device__ __forceinline__ float tanh_fast(float x) {
    return fmaf(2.0f, sig_fast(2.0f * x), -1.0f);
}

// Tiled matvec: g[256 x NB] = Wt[K x 256]^T-view  *  hh[K x NB]
// thread (r4 = tid>>2 in [0,64), c4 = tid&3): rows 4*r4..+3, batches 8*c4..+7
template<int K>
static __device__ __forceinline__ void matvec(const float* __restrict__ Wt,
                                              const float* __restrict__ hh,
                                              float* __restrict__ gsh,
                                              int r4, int c4)
{
    ull A0=0,A1=0,A2=0,A3=0, B0=0,B1=0,B2=0,B3=0;
    ull C0=0,C1=0,C2=0,C3=0, D0=0,D1=0,D2=0,D3=0;
    const float4*      wp = (const float4*)Wt + r4;            // + k*64 per k
    const ulonglong2*  hp = (const ulonglong2*)hh + (c4 << 1); // + k*8  per k

    #pragma unroll 8
    for (int k = 0; k < K; k++) {
        float4     w  = wp[k * 64];
        ulonglong2 hA = hp[k * 8];
        ulonglong2 hB = hp[k * 8 + 1];
        ull w0 = splat(w.x), w1 = splat(w.y), w2 = splat(w.z), w3 = splat(w.w);
        ffma2(A0,w0,hA.x); ffma2(A1,w0,hA.y); ffma2(A2,w0,hB.x); ffma2(A3,w0,hB.y);
        ffma2(B0,w1,hA.x); ffma2(B1,w1,hA.y); ffma2(B2,w1,hB.x); ffma2(B3,w1,hB.y);
        ffma2(C0,w2,hA.x); ffma2(C1,w2,hA.y); ffma2(C2,w2,hB.x); ffma2(C3,w2,hB.y);
        ffma2(D0,w3,hA.x); ffma2(D1,w3,hA.y); ffma2(D2,w3,hB.x); ffma2(D3,w3,hB.y);
    }
    float* g0 = gsh + (r4 << 2) * GSTR + (c4 << 3);
    ((ulonglong2*)(g0          ))[0] = make_ulonglong2(A0, A1);
    ((ulonglong2*)(g0 + 4      ))[0] = make_ulonglong2(A2, A3);
    ((ulonglong2*)(g0 + GSTR   ))[0] = make_ulonglong2(B0, B1);
    ((ulonglong2*)(g0 + GSTR+4 ))[0] = make_ulonglong2(B2, B3);
    ((ulonglong2*)(g0 + 2*GSTR ))[0] = make_ulonglong2(C0, C1);
    ((ulonglong2*)(g0 + 2*GSTR+4))[0] = make_ulonglong2(C2, C3);
    ((ulonglong2*)(g0 + 3*GSTR ))[0] = make_ulonglong2(D0, D1);
    ((ulonglong2*)(g0 + 3*GSTR+4))[0] = make_ulonglong2(D2, D3);
}

__global__ void __launch_bounds__(NTHR, 1)
lstm_rec_kernel(const float* __restrict__ x,
                const float* __restrict__ Wih1, const float* __restrict__ Whh1,
                const float* __restrict__ bih1, const float* __restrict__ bhh1,
                const float* __restrict__ Wih2, const float* __restrict__ Whh2,
                const float* __restrict__ bih2, const float* __restrict__ bhh2,
                const float* __restrict__ fc1w, const float* __restrict__ fc1b,
                const float* __restrict__ fc2w, const float* __restrict__ fc2b,
                float* __restrict__ out)
{
    extern __shared__ float sm[];
    float* Wt    = sm;               // [128][256]   32768
    float* hh    = Wt + 32768;       // [128][NB]    4096  (rows 0..63: r1/x-h1, 64..127: h2)
    float* gsh   = hh + 4096;        // [256][GSTR]  9216
    float* win   = gsh + 9216;       // [NB][WSTR]   6176
    float* b1s   = win + NB * WSTR;  // 256
    float* wi1s  = b1s + 256;        // 256
    float* b2s   = wi1s + 256;       // 256
    float* wcomb = b2s + 256;        // 65
    float* bcs   = wcomb + 65;       // 1
    float* dsh   = bcs + 1;          // NB

    const int tid = threadIdx.x;
    const int b0  = blockIdx.x * NB;
    const int r4  = tid >> 2, c4 = tid & 3;   // matvec role
    const int ab  = tid & 31, au0 = tid >> 5; // activation role: batch ab, units au0+8q

    // ---------------- one-time init ----------------
    for (int i = tid; i < NB * TLEN; i += NTHR) {
        int b = i / TLEN, t = i - b * TLEN;
        win[b * WSTR + t] = x[(size_t)(b0 + b) * SEQ + t];
    }
    if (tid < NB) dsh[tid] = x[(size_t)(b0 + tid) * SEQ + TLEN];
    b1s[tid]  = bih1[tid] + bhh1[tid];
    wi1s[tid] = Wih1[tid];
    b2s[tid]  = bih2[tid] + bhh2[tid];
    if (tid < 65) {
        float s = 0.0f;
        for (int j = 0; j < 64; j++) s = fmaf(fc2w[j], fc1w[j * 65 + tid], s);
        wcomb[tid] = s;
    }
    if (tid == 65) {
        float s = fc2b[0];
        for (int j = 0; j < 64; j++) s = fmaf(fc2w[j], fc1b[j], s);
        *bcs = s;
    }

    float cst[8], r1n[8];
    __syncthreads();

    for (int step = 0; step < NSTEPS; step++) {
        // ---- stage W1 (transposed), zero h1, zero c ----
        for (int i = tid; i < 256 * 64; i += NTHR) {
            int row = i >> 6, kk = i & 63;
            Wt[kk * 256 + row] = Whh1[i];
        }
        for (int i = tid; i < 64 * NB; i += NTHR) hh[i] = 0.0f;
        #pragma unroll
        for (int q = 0; q < 8; q++) cst[q] = 0.0f;
        __syncthreads();

        // ============ layer 1 recurrence ============
        for (int t = 0; t < TLEN; t++) {
            matvec<64>(Wt, hh, gsh, r4, c4);
            __syncthreads();
            float xt = win[ab * WSTR + step + t];
            size_t gb = ((size_t)blockIdx.x * TLEN + t) * 64;
            #pragma unroll
            for (int q = 0; q < 8; q++) {
                int u = au0 + (q << 3);
                float gi = gsh[u * GSTR + ab]         + fmaf(xt, wi1s[u],       b1s[u]);
                float gf = gsh[(u + 64) * GSTR + ab]  + fmaf(xt, wi1s[u + 64],  b1s[u + 64]);
                float gg = gsh[(u + 128) * GSTR + ab] + fmaf(xt, wi1s[u + 128], b1s[u + 128]);
                float go = gsh[(u + 192) * GSTR + ab] + fmaf(xt, wi1s[u + 192], b1s[u + 192]);
                float cn = fmaf(sig_fast(gf), cst[q], sig_fast(gi) * tanh_fast(gg));
                cst[q] = cn;
                float h = sig_fast(go) * tanh_fast(cn);
                hh[u * NB + ab] = h;
                g_r1[(gb + u) * NB + ab] = fmaxf(h, 0.0f);
            }
            __syncthreads();
        }

        // ---- transition: h2_0 = h1_T, rows 0..63 <- r1_0; stage W2 ----
        float h1T[8];
        #pragma unroll
        for (int q = 0; q < 8; q++) {
            int u = au0 + (q << 3);
            h1T[q] = hh[u * NB + ab];                        // own writes, no race
            r1n[q] = g_r1[((size_t)blockIdx.x * TLEN * 64 + u) * NB + ab];
        }
        for (int i = tid; i < 256 * 64; i += NTHR) {
            int row = i >> 6, kk = i & 63;
            float v1 = Wih2[i], v2 = Whh2[i];
            Wt[kk * 256 + row]        = v1;
            Wt[(kk + 64) * 256 + row] = v2;
        }
        #pragma unroll
        for (int q = 0; q < 8; q++) {
            int u = au0 + (q << 3);
            hh[(64 + u) * NB + ab] = h1T[q];
            hh[u * NB + ab]        = r1n[q];
        }
        __syncthreads();

        // ============ layer 2 recurrence ============
        for (int t = 0; t < TLEN; t++) {
            if (t + 1 < TLEN) {   // prefetch r1[t+1] under the matvec
                size_t gb = ((size_t)blockIdx.x * TLEN + (t + 1)) * 64;
                #pragma unroll
                for (int q = 0; q < 8; q++) {
                    int u = au0 + (q << 3);
                    r1n[q] = g_r1[(gb + u) * NB + ab];
                }
            }
            matvec<128>(Wt, hh, gsh, r4, c4);
            __syncthreads();
            #pragma unroll
            for (int q = 0; q < 8; q++) {
                int u = au0 + (q << 3);
                float gi = gsh[u * GSTR + ab]         + b2s[u];
                float gf = gsh[(u + 64) * GSTR + ab]  + b2s[u + 64];
                float gg = gsh[(u + 128) * GSTR + ab] + b2s[u + 128];
                float go = gsh[(u + 192) * GSTR + ab] + b2s[u + 192];
                float cn = fmaf(sig_fast(gf), cst[q], sig_fast(gi) * tanh_fast(gg));
                cst[q] = cn;
                hh[(64 + u) * NB + ab] = sig_fast(go) * tanh_fast(cn);
                if (t + 1 < TLEN) hh[u * NB + ab] = r1n[q];
            }
            __syncthreads();
        }

        // ============ FC (collapsed) + window append ============
        if (tid < NB) {
            float s = *bcs + wcomb[64] * dsh[tid];
            #pragma unroll
            for (int u = 0; u < 64; u++)
                s = fmaf(wcomb[u], fmaxf(hh[(64 + u) * NB + tid], 0.0f), s);
            out[(size_t)(b0 + tid) * NSTEPS + step] = s;
            win[tid * WSTR + TLEN + step] = s;
        }
        __syncthreads();
    }
}

extern "C" void kernel_launch(void* const* d_in, const int* in_sizes, int n_in,
                              void* d_out, int out_size) {
    (void)in_sizes; (void)n_in; (void)out_size;
    const float* x    = (const float*)d_in[0];
    const float* Wih1 = (const float*)d_in[1];
    const float* Whh1 = (const float*)d_in[2];
    const float* bih1 = (const float*)d_in[3];
    const float* bhh1 = (const float*)d_in[4];
    const float* Wih2 = (const float*)d_in[5];
    const float* Whh2 = (const float*)d_in[6];
    const float* bih2 = (const float*)d_in[7];
    const float* bhh2 = (const float*)d_in[8];
    const float* fc1w = (const float*)d_in[9];
    const float* fc1b = (const float*)d_in[10];
    const float* fc2w = (const float*)d_in[11];
    const float* fc2b = (const float*)d_in[12];
    float* out = (float*)d_out;

    size_t smem = (size_t)(32768 + 4096 + 9216 + NB * WSTR + 256 * 3 + 65 + 1 + NB) * sizeof(float);
    cudaFuncSetAttribute(lstm_rec_kernel, cudaFuncAttributeMaxDynamicSharedMemorySize, (int)smem);
    lstm_rec_kernel<<<GRID, NTHR, smem>>>(x, Wih1, Whh1, bih1, bhh1,
                                          Wih2, Whh2, bih2, bhh2,
                                          fc1w, fc1b, fc2w, fc2b, out);
}